// round 3
// baseline (speedup 1.0000x reference)
#include <cuda_runtime.h>

#define N_NODES 50000
#define N_EDGES 50000
#define CIN 256
#define COUT 128

// ---------------- scratch (static device globals; no allocation) ----------------
// 16-byte alignment REQUIRED: accessed via float4* and red.v4.f32.
__device__ __align__(16) float g_x[(size_t)N_NODES * COUT];      // product @ lin_w
__device__ __align__(16) float g_edge[(size_t)N_EDGES * COUT];   // per-hyperedge accumulator
__device__ __align__(16) float g_degD[2][N_NODES];               // node degree per view
__device__ __align__(16) float g_degB[2][N_EDGES];               // edge degree per view

// ---------------- GEMM: x = A[50000,256] @ W[256,128] ----------------
__global__ void __launch_bounds__(256) gemm_kernel(const float* __restrict__ A,
                                                   const float* __restrict__ W) {
    __shared__ __align__(16) float As[16][132];   // [k][m], padded
    __shared__ __align__(16) float Bs[16][128];   // [k][n]

    const int tid = threadIdx.x;
    const int m0 = blockIdx.x * 128;
    const int ty = tid >> 4;        // 0..15
    const int tx = tid & 15;        // 0..15

    float acc[8][8];
#pragma unroll
    for (int i = 0; i < 8; i++)
#pragma unroll
        for (int j = 0; j < 8; j++) acc[i][j] = 0.0f;

    for (int k0 = 0; k0 < CIN; k0 += 16) {
#pragma unroll
        for (int l = 0; l < 2; l++) {
            int f = tid * 2 + l;                  // 0..511
            int arow = f >> 2;
            int akc = (f & 3) << 2;
            float4 a = make_float4(0.f, 0.f, 0.f, 0.f);
            if (m0 + arow < N_NODES)
                a = *reinterpret_cast<const float4*>(&A[(size_t)(m0 + arow) * CIN + k0 + akc]);
            As[akc + 0][arow] = a.x;
            As[akc + 1][arow] = a.y;
            As[akc + 2][arow] = a.z;
            As[akc + 3][arow] = a.w;
            int brow = f >> 5;
            int bcol = (f & 31) << 2;
            *reinterpret_cast<float4*>(&Bs[brow][bcol]) =
                *reinterpret_cast<const float4*>(&W[(size_t)(k0 + brow) * COUT + bcol]);
        }
        __syncthreads();

#pragma unroll
        for (int k = 0; k < 16; k++) {
            float a[8], b[8];
            *reinterpret_cast<float4*>(&a[0]) = *reinterpret_cast<const float4*>(&As[k][ty * 8]);
            *reinterpret_cast<float4*>(&a[4]) = *reinterpret_cast<const float4*>(&As[k][ty * 8 + 4]);
            *reinterpret_cast<float4*>(&b[0]) = *reinterpret_cast<const float4*>(&Bs[k][tx * 8]);
            *reinterpret_cast<float4*>(&b[4]) = *reinterpret_cast<const float4*>(&Bs[k][tx * 8 + 4]);
#pragma unroll
            for (int i = 0; i < 8; i++)
#pragma unroll
                for (int j = 0; j < 8; j++) acc[i][j] += a[i] * b[j];
        }
        __syncthreads();
    }

#pragma unroll
    for (int i = 0; i < 8; i++) {
        int r = m0 + ty * 8 + i;
        if (r < N_NODES) {
            float4 v0 = make_float4(acc[i][0], acc[i][1], acc[i][2], acc[i][3]);
            float4 v1 = make_float4(acc[i][4], acc[i][5], acc[i][6], acc[i][7]);
            *reinterpret_cast<float4*>(&g_x[(size_t)r * COUT + tx * 8]) = v0;
            *reinterpret_cast<float4*>(&g_x[(size_t)r * COUT + tx * 8 + 4]) = v1;
        }
    }
}

// ---------------- init / zero kernels ----------------
__global__ void zero_degs_kernel() {
    int i = blockIdx.x * blockDim.x + threadIdx.x;
    if (i < N_NODES) {
        g_degD[0][i] = 0.f;
        g_degD[1][i] = 0.f;
        g_degB[0][i] = 0.f;
        g_degB[1][i] = 0.f;
    }
}

__global__ void zero_edge_kernel() {
    int i = blockIdx.x * blockDim.x + threadIdx.x;
    if (i < (N_EDGES * COUT) / 4)
        reinterpret_cast<float4*>(g_edge)[i] = make_float4(0.f, 0.f, 0.f, 0.f);
}

__global__ void init_out_kernel(const float* __restrict__ bias, float* __restrict__ out) {
    int i = blockIdx.x * blockDim.x + threadIdx.x;
    if (i < (N_NODES * COUT) / 4) {
        reinterpret_cast<float4*>(out)[i] =
            reinterpret_cast<const float4*>(bias)[i & (COUT / 4 - 1)];
    }
}

// ---------------- degree histograms (both views, one pass) ----------------
// Index arrays are INT32 (JAX x64 disabled: jnp.int64 silently -> int32).
__global__ void degrees_kernel(const int* __restrict__ av,
                               const int* __restrict__ ab, int E) {
    int stride = gridDim.x * blockDim.x;
    for (int i = blockIdx.x * blockDim.x + threadIdx.x; i < E; i += stride) {
        atomicAdd(&g_degD[0][av[i]], 1.0f);
        atomicAdd(&g_degB[0][av[E + i]], 1.0f);
        atomicAdd(&g_degD[1][ab[i]], 1.0f);
        atomicAdd(&g_degB[1][ab[E + i]], 1.0f);
    }
}

// ---------------- vector red helper ----------------
__device__ __forceinline__ void red_add_v4(float* ptr, float4 v) {
    asm volatile("red.global.add.v4.f32 [%0], {%1, %2, %3, %4};"
                 :: "l"(ptr), "f"(v.x), "f"(v.y), "f"(v.z), "f"(v.w)
                 : "memory");
}

// ---------------- scatter pass 1: nodes -> hyperedges ----------------
// One warp per incidence pair: lane handles float4 (32 lanes * 4 = 128 = COUT).
__global__ void scatter_n2e_kernel(const int* __restrict__ idx, int E) {
    const int lane = threadIdx.x & 31;
    const int warp = (blockIdx.x * blockDim.x + threadIdx.x) >> 5;
    const int nwarps = (gridDim.x * blockDim.x) >> 5;
    for (int p = warp; p < E; p += nwarps) {
        int n = __ldg(&idx[p]);
        int e = __ldg(&idx[E + p]);
        float4 v = *reinterpret_cast<const float4*>(&g_x[(size_t)n * COUT + lane * 4]);
        red_add_v4(&g_edge[(size_t)e * COUT + lane * 4], v);
    }
}

// ---------------- scatter pass 2: hyperedges -> nodes (fused scaling) ----------------
// out[n] += 0.5 * D_inv[n] * B_inv[e] * edge_feat[e]
__global__ void scatter_e2n_kernel(const int* __restrict__ idx, int E, int view,
                                   float* __restrict__ out) {
    const int lane = threadIdx.x & 31;
    const int warp = (blockIdx.x * blockDim.x + threadIdx.x) >> 5;
    const int nwarps = (gridDim.x * blockDim.x) >> 5;
    for (int p = warp; p < E; p += nwarps) {
        int n = __ldg(&idx[p]);
        int e = __ldg(&idx[E + p]);
        float d = g_degD[view][n];
        float b = g_degB[view][e];
        float coef = 0.5f;
        coef = (d > 0.f) ? __fdividef(coef, d) : 0.f;
        coef = (b > 0.f) ? __fdividef(coef, b) : 0.f;
        float4 v = *reinterpret_cast<const float4*>(&g_edge[(size_t)e * COUT + lane * 4]);
        v.x *= coef; v.y *= coef; v.z *= coef; v.w *= coef;
        red_add_v4(&out[(size_t)n * COUT + lane * 4], v);
    }
}

// ---------------- launcher ----------------
extern "C" void kernel_launch(void* const* d_in, const int* in_sizes, int n_in,
                              void* d_out, int out_size) {
    const float* product   = (const float*)d_in[0];
    const float* category  = (const float*)d_in[1];
    const float* av_feat   = (const float*)d_in[2];
    const int* also_view   = (const int*)d_in[3];   // int32 (JAX default x64 off)
    const int* also_buy    = (const int*)d_in[4];
    const float* lin_w     = (const float*)d_in[5];
    const float* bias      = (const float*)d_in[6];
    float* out = (float*)d_out;

    const int E = in_sizes[3] / 2;
    const int cat_elems = in_sizes[1];
    const int av_elems = in_sizes[2];

    // 1. GEMM x = product @ lin_w
    gemm_kernel<<<(N_NODES + 127) / 128, 256>>>(product, lin_w);

    // 2. degrees
    zero_degs_kernel<<<(N_NODES + 255) / 256, 256>>>();
    degrees_kernel<<<2048, 256>>>(also_view, also_buy, E);

    // 3. init output (bias) for product block
    init_out_kernel<<<((N_NODES * COUT / 4) + 255) / 256, 256>>>(bias, out);

    const int SC_BLOCKS = 2048;  // 16384 warps, grid-stride

    // 4. view 0: also_view
    zero_edge_kernel<<<((N_EDGES * COUT / 4) + 255) / 256, 256>>>();
    scatter_n2e_kernel<<<SC_BLOCKS, 256>>>(also_view, E);
    scatter_e2n_kernel<<<SC_BLOCKS, 256>>>(also_view, E, 0, out);

    // 5. view 1: also_buy
    zero_edge_kernel<<<((N_EDGES * COUT / 4) + 255) / 256, 256>>>();
    scatter_n2e_kernel<<<SC_BLOCKS, 256>>>(also_buy, E);
    scatter_e2n_kernel<<<SC_BLOCKS, 256>>>(also_buy, E, 1, out);

    // 6. passthrough outputs: category, av
    cudaMemcpyAsync(out + (size_t)N_NODES * COUT, category,
                    (size_t)cat_elems * sizeof(float), cudaMemcpyDeviceToDevice, 0);
    cudaMemcpyAsync(out + (size_t)N_NODES * COUT + cat_elems, av_feat,
                    (size_t)av_elems * sizeof(float), cudaMemcpyDeviceToDevice, 0);
}

// round 5
// speedup vs baseline: 1.5165x; 1.5165x over previous
#include <cuda_runtime.h>

#define N_NODES 50000
#define N_EDGES 50000
#define CIN 256
#define COUT 128
#define MAXE 1600000

// ---------------- scratch (static device globals; ~58.4 MB total) ----------------
__device__ __align__(16) float g_x[(size_t)N_NODES * COUT];     // 25.6 MB
__device__ __align__(16) float g_edge[(size_t)N_EDGES * COUT];  // 25.6 MB (reused per view)
__device__ int g_ecnt[N_EDGES];                                 // count, then fill cursor
__device__ int g_ncnt[N_NODES];
__device__ int g_eoff[N_EDGES + 1];
__device__ int g_noff[N_NODES + 1];
__device__ unsigned short g_eadj[MAXE];                         // 3.2 MB: node ids by edge
__device__ unsigned short g_nadj[MAXE];                         // 3.2 MB: edge ids by node

// ---------------- GEMM: x = A[50000,256] @ W[256,128] ----------------
__global__ void __launch_bounds__(256) gemm_kernel(const float* __restrict__ A,
                                                   const float* __restrict__ W) {
    __shared__ __align__(16) float As[16][132];
    __shared__ __align__(16) float Bs[16][128];

    const int tid = threadIdx.x;
    const int m0 = blockIdx.x * 128;
    const int ty = tid >> 4;
    const int tx = tid & 15;

    float acc[8][8];
#pragma unroll
    for (int i = 0; i < 8; i++)
#pragma unroll
        for (int j = 0; j < 8; j++) acc[i][j] = 0.0f;

    for (int k0 = 0; k0 < CIN; k0 += 16) {
#pragma unroll
        for (int l = 0; l < 2; l++) {
            int f = tid * 2 + l;
            int arow = f >> 2;
            int akc = (f & 3) << 2;
            float4 a = make_float4(0.f, 0.f, 0.f, 0.f);
            if (m0 + arow < N_NODES)
                a = *reinterpret_cast<const float4*>(&A[(size_t)(m0 + arow) * CIN + k0 + akc]);
            As[akc + 0][arow] = a.x;
            As[akc + 1][arow] = a.y;
            As[akc + 2][arow] = a.z;
            As[akc + 3][arow] = a.w;
            int brow = f >> 5;
            int bcol = (f & 31) << 2;
            *reinterpret_cast<float4*>(&Bs[brow][bcol]) =
                *reinterpret_cast<const float4*>(&W[(size_t)(k0 + brow) * COUT + bcol]);
        }
        __syncthreads();
#pragma unroll
        for (int k = 0; k < 16; k++) {
            float a[8], b[8];
            *reinterpret_cast<float4*>(&a[0]) = *reinterpret_cast<const float4*>(&As[k][ty * 8]);
            *reinterpret_cast<float4*>(&a[4]) = *reinterpret_cast<const float4*>(&As[k][ty * 8 + 4]);
            *reinterpret_cast<float4*>(&b[0]) = *reinterpret_cast<const float4*>(&Bs[k][tx * 8]);
            *reinterpret_cast<float4*>(&b[4]) = *reinterpret_cast<const float4*>(&Bs[k][tx * 8 + 4]);
#pragma unroll
            for (int i = 0; i < 8; i++)
#pragma unroll
                for (int j = 0; j < 8; j++) acc[i][j] += a[i] * b[j];
        }
        __syncthreads();
    }

#pragma unroll
    for (int i = 0; i < 8; i++) {
        int r = m0 + ty * 8 + i;
        if (r < N_NODES) {
            *reinterpret_cast<float4*>(&g_x[(size_t)r * COUT + tx * 8]) =
                make_float4(acc[i][0], acc[i][1], acc[i][2], acc[i][3]);
            *reinterpret_cast<float4*>(&g_x[(size_t)r * COUT + tx * 8 + 4]) =
                make_float4(acc[i][4], acc[i][5], acc[i][6], acc[i][7]);
        }
    }
}

// ---------------- CSR construction (one view at a time) ----------------
__global__ void zero_cnt_kernel() {
    int i = blockIdx.x * blockDim.x + threadIdx.x;
    if (i < N_EDGES) g_ecnt[i] = 0;
    if (i < N_NODES) g_ncnt[i] = 0;
}

__global__ void count_kernel(const int* __restrict__ idx, int E) {
    int stride = gridDim.x * blockDim.x;
    for (int i = blockIdx.x * blockDim.x + threadIdx.x; i < E; i += stride) {
        atomicAdd(&g_ncnt[idx[i]], 1);
        atomicAdd(&g_ecnt[idx[E + i]], 1);
    }
}

// 2 blocks: exclusive scan of cnt -> off; cnt becomes the fill cursor.
__global__ void __launch_bounds__(1024) scan_kernel() {
    int* cnt; int* off; int N;
    if (blockIdx.x == 0) { cnt = g_ecnt; off = g_eoff; N = N_EDGES; }
    else                 { cnt = g_ncnt; off = g_noff; N = N_NODES; }

    __shared__ int warp_sums[32];
    __shared__ int carry_s;
    const int tid = threadIdx.x;
    const int lane = tid & 31, wid = tid >> 5;
    if (tid == 0) carry_s = 0;
    __syncthreads();

    for (int c0 = 0; c0 < N; c0 += 1024) {
        int i = c0 + tid;
        int v = (i < N) ? cnt[i] : 0;
        int s = v;
#pragma unroll
        for (int d = 1; d < 32; d <<= 1) {
            int t = __shfl_up_sync(0xffffffffu, s, d);
            if (lane >= d) s += t;
        }
        if (lane == 31) warp_sums[wid] = s;
        __syncthreads();
        if (wid == 0) {
            int w = warp_sums[lane];
#pragma unroll
            for (int d = 1; d < 32; d <<= 1) {
                int t = __shfl_up_sync(0xffffffffu, w, d);
                if (lane >= d) w += t;
            }
            warp_sums[lane] = w;
        }
        __syncthreads();
        int excl = s - v + (wid > 0 ? warp_sums[wid - 1] : 0) + carry_s;
        if (i < N) { off[i] = excl; cnt[i] = excl; }   // cnt := cursor
        __syncthreads();
        if (tid == 1023) carry_s = excl + v;
        __syncthreads();
    }
    if (tid == 0) off[N] = carry_s;
}

__global__ void fill_kernel(const int* __restrict__ idx, int E) {
    int stride = gridDim.x * blockDim.x;
    for (int i = blockIdx.x * blockDim.x + threadIdx.x; i < E; i += stride) {
        int n = idx[i], e = idx[E + i];
        g_eadj[atomicAdd(&g_ecnt[e], 1)] = (unsigned short)n;
        g_nadj[atomicAdd(&g_ncnt[n], 1)] = (unsigned short)e;
    }
}

// ---------------- pass 1: nodes -> hyperedges (gather, one store per edge) ------
__global__ void __launch_bounds__(256) n2e_kernel() {
    const int e = (blockIdx.x * blockDim.x + threadIdx.x) >> 5;
    if (e >= N_EDGES) return;
    const int lane = threadIdx.x & 31;
    const int base = g_eoff[e], end = g_eoff[e + 1];

    float4 acc = make_float4(0.f, 0.f, 0.f, 0.f);
    for (int j0 = base; j0 < end; j0 += 32) {
        const int cnt = min(32, end - j0);
        const int myid = (lane < cnt) ? (int)g_eadj[j0 + lane] : 0;
        for (int t = 0; t < cnt; t++) {
            const int nid = __shfl_sync(0xffffffffu, myid, t);
            const float4 v = *reinterpret_cast<const float4*>(&g_x[(size_t)nid * COUT + lane * 4]);
            acc.x += v.x; acc.y += v.y; acc.z += v.z; acc.w += v.w;
        }
    }
    const float s = (end > base) ? __fdividef(1.f, (float)(end - base)) : 0.f;
    acc.x *= s; acc.y *= s; acc.z *= s; acc.w *= s;
    *reinterpret_cast<float4*>(&g_edge[(size_t)e * COUT + lane * 4]) = acc;
}

// ---------------- pass 2: hyperedges -> nodes ----------------
// first=1: out = bias + 0.5*sum ; first=0: out += 0.5*sum (warp owns row; no atomics)
__global__ void __launch_bounds__(256) e2n_kernel(const float* __restrict__ bias,
                                                  float* __restrict__ out, int first) {
    const int n = (blockIdx.x * blockDim.x + threadIdx.x) >> 5;
    if (n >= N_NODES) return;
    const int lane = threadIdx.x & 31;
    const int base = g_noff[n], end = g_noff[n + 1];

    float4 acc = make_float4(0.f, 0.f, 0.f, 0.f);
    for (int j0 = base; j0 < end; j0 += 32) {
        const int cnt = min(32, end - j0);
        const int myid = (lane < cnt) ? (int)g_nadj[j0 + lane] : 0;
        for (int t = 0; t < cnt; t++) {
            const int eid = __shfl_sync(0xffffffffu, myid, t);
            const float4 w = *reinterpret_cast<const float4*>(&g_edge[(size_t)eid * COUT + lane * 4]);
            acc.x += w.x; acc.y += w.y; acc.z += w.z; acc.w += w.w;
        }
    }
    const float c = (end > base) ? __fdividef(0.5f, (float)(end - base)) : 0.f;
    float4 r;
    if (first) r = *reinterpret_cast<const float4*>(&bias[lane * 4]);
    else       r = *reinterpret_cast<const float4*>(&out[(size_t)n * COUT + lane * 4]);
    r.x += c * acc.x; r.y += c * acc.y; r.z += c * acc.z; r.w += c * acc.w;
    *reinterpret_cast<float4*>(&out[(size_t)n * COUT + lane * 4]) = r;
}

// ---------------- launcher ----------------
extern "C" void kernel_launch(void* const* d_in, const int* in_sizes, int n_in,
                              void* d_out, int out_size) {
    const float* product  = (const float*)d_in[0];
    const float* category = (const float*)d_in[1];
    const float* av_feat  = (const float*)d_in[2];
    const int* also_view  = (const int*)d_in[3];   // int32
    const int* also_buy   = (const int*)d_in[4];
    const float* lin_w    = (const float*)d_in[5];
    const float* bias     = (const float*)d_in[6];
    float* out = (float*)d_out;

    const int E = in_sizes[3] / 2;
    const int cat_elems = in_sizes[1];
    const int av_elems = in_sizes[2];

    // GEMM x = product @ lin_w
    gemm_kernel<<<(N_NODES + 127) / 128, 256>>>(product, lin_w);

    const int WB = (N_EDGES * 32 + 255) / 256;   // warp-per-row grids
    const int NB = (N_NODES * 32 + 255) / 256;

    // ---- view 0: also_view ----
    zero_cnt_kernel<<<(N_EDGES + 255) / 256, 256>>>();
    count_kernel<<<1024, 256>>>(also_view, E);
    scan_kernel<<<2, 1024>>>();
    fill_kernel<<<1024, 256>>>(also_view, E);
    n2e_kernel<<<WB, 256>>>();
    e2n_kernel<<<NB, 256>>>(bias, out, 1);

    // ---- view 1: also_buy (reuses all CSR buffers + g_edge) ----
    zero_cnt_kernel<<<(N_EDGES + 255) / 256, 256>>>();
    count_kernel<<<1024, 256>>>(also_buy, E);
    scan_kernel<<<2, 1024>>>();
    fill_kernel<<<1024, 256>>>(also_buy, E);
    n2e_kernel<<<WB, 256>>>();
    e2n_kernel<<<NB, 256>>>(bias, out, 0);

    // passthrough outputs: category, av
    cudaMemcpyAsync(out + (size_t)N_NODES * COUT, category,
                    (size_t)cat_elems * sizeof(float), cudaMemcpyDeviceToDevice, 0);
    cudaMemcpyAsync(out + (size_t)N_NODES * COUT + cat_elems, av_feat,
                    (size_t)av_elems * sizeof(float), cudaMemcpyDeviceToDevice, 0);
}

// round 7
// speedup vs baseline: 1.6694x; 1.1008x over previous
#include <cuda_runtime.h>
#include <cuda_fp16.h>

#define N_NODES 50000
#define N_EDGES 50000
#define CIN 256
#define COUT 128
#define MAXE 1600000

// ---------------- scratch (static device globals; ~34 MB total) ----------------
__device__ __align__(16) __half g_x[(size_t)N_NODES * COUT];     // 12.8 MB (fp16)
__device__ __align__(16) __half g_edge[(size_t)N_EDGES * COUT];  // 12.8 MB (fp16, reused per view)
__device__ int g_ecnt[2][N_EDGES];                               // count -> fill cursor
__device__ int g_ncnt[2][N_NODES];
__device__ int g_eoff[2][N_EDGES + 1];
__device__ int g_noff[2][N_NODES + 1];
__device__ unsigned short g_eadj[MAXE];                          // node ids by edge (per-view reuse)
__device__ unsigned short g_nadj[MAXE];                          // edge ids by node (per-view reuse)

// ---------------- GEMM: x = A[50000,256] @ W[256,128] -> fp16 ----------------
__global__ void __launch_bounds__(256) gemm_kernel(const float* __restrict__ A,
                                                   const float* __restrict__ W) {
    __shared__ __align__(16) float As[16][132];
    __shared__ __align__(16) float Bs[16][128];

    const int tid = threadIdx.x;
    const int m0 = blockIdx.x * 128;
    const int ty = tid >> 4;
    const int tx = tid & 15;

    float acc[8][8];
#pragma unroll
    for (int i = 0; i < 8; i++)
#pragma unroll
        for (int j = 0; j < 8; j++) acc[i][j] = 0.0f;

    for (int k0 = 0; k0 < CIN; k0 += 16) {
#pragma unroll
        for (int l = 0; l < 2; l++) {
            int f = tid * 2 + l;
            int arow = f >> 2;
            int akc = (f & 3) << 2;
            float4 a = make_float4(0.f, 0.f, 0.f, 0.f);
            if (m0 + arow < N_NODES)
                a = *reinterpret_cast<const float4*>(&A[(size_t)(m0 + arow) * CIN + k0 + akc]);
            As[akc + 0][arow] = a.x;
            As[akc + 1][arow] = a.y;
            As[akc + 2][arow] = a.z;
            As[akc + 3][arow] = a.w;
            int brow = f >> 5;
            int bcol = (f & 31) << 2;
            *reinterpret_cast<float4*>(&Bs[brow][bcol]) =
                *reinterpret_cast<const float4*>(&W[(size_t)(k0 + brow) * COUT + bcol]);
        }
        __syncthreads();
#pragma unroll
        for (int k = 0; k < 16; k++) {
            float a[8], b[8];
            *reinterpret_cast<float4*>(&a[0]) = *reinterpret_cast<const float4*>(&As[k][ty * 8]);
            *reinterpret_cast<float4*>(&a[4]) = *reinterpret_cast<const float4*>(&As[k][ty * 8 + 4]);
            *reinterpret_cast<float4*>(&b[0]) = *reinterpret_cast<const float4*>(&Bs[k][tx * 8]);
            *reinterpret_cast<float4*>(&b[4]) = *reinterpret_cast<const float4*>(&Bs[k][tx * 8 + 4]);
#pragma unroll
            for (int i = 0; i < 8; i++)
#pragma unroll
                for (int j = 0; j < 8; j++) acc[i][j] += a[i] * b[j];
        }
        __syncthreads();
    }

#pragma unroll
    for (int i = 0; i < 8; i++) {
        int r = m0 + ty * 8 + i;
        if (r < N_NODES) {
            __half2 h01 = __floats2half2_rn(acc[i][0], acc[i][1]);
            __half2 h23 = __floats2half2_rn(acc[i][2], acc[i][3]);
            __half2 h45 = __floats2half2_rn(acc[i][4], acc[i][5]);
            __half2 h67 = __floats2half2_rn(acc[i][6], acc[i][7]);
            uint4 o;
            o.x = *reinterpret_cast<unsigned int*>(&h01);
            o.y = *reinterpret_cast<unsigned int*>(&h23);
            o.z = *reinterpret_cast<unsigned int*>(&h45);
            o.w = *reinterpret_cast<unsigned int*>(&h67);
            *reinterpret_cast<uint4*>(&g_x[(size_t)r * COUT + tx * 8]) = o;
        }
    }
}

// ---------------- CSR construction (both views) ----------------
__global__ void zero_cnt_kernel() {
    int i = blockIdx.x * blockDim.x + threadIdx.x;
    if (i < N_EDGES) { g_ecnt[0][i] = 0; g_ecnt[1][i] = 0; }
    if (i < N_NODES) { g_ncnt[0][i] = 0; g_ncnt[1][i] = 0; }
}

__global__ void count_kernel(const int* __restrict__ av, const int* __restrict__ ab, int E) {
    int stride = gridDim.x * blockDim.x;
    for (int i = blockIdx.x * blockDim.x + threadIdx.x; i < E; i += stride) {
        atomicAdd(&g_ncnt[0][av[i]], 1);
        atomicAdd(&g_ecnt[0][av[E + i]], 1);
        atomicAdd(&g_ncnt[1][ab[i]], 1);
        atomicAdd(&g_ecnt[1][ab[E + i]], 1);
    }
}

// 4 blocks, one per array. Two-pass register scan: thread sums C elems,
// block-scans 1024 sums via shuffles, then re-walks and emits off+cursor.
__global__ void __launch_bounds__(1024) scan4_kernel() {
    const int a = blockIdx.x;
    int* cnt; int* off; const int N = 50000;
    if (a == 0)      { cnt = g_ecnt[0]; off = g_eoff[0]; }
    else if (a == 1) { cnt = g_ecnt[1]; off = g_eoff[1]; }
    else if (a == 2) { cnt = g_ncnt[0]; off = g_noff[0]; }
    else             { cnt = g_ncnt[1]; off = g_noff[1]; }

    const int C = (N + 1023) / 1024;        // 49
    const int tid = threadIdx.x;
    const int lane = tid & 31, wid = tid >> 5;
    const int start = tid * C;

    // pass 1: thread-local sum
    int tsum = 0;
#pragma unroll 7
    for (int j = 0; j < C; j++) {
        int i = start + j;
        if (i < N) tsum += cnt[i];
    }
    // block exclusive scan of tsum
    int s = tsum;
#pragma unroll
    for (int d = 1; d < 32; d <<= 1) {
        int t = __shfl_up_sync(0xffffffffu, s, d);
        if (lane >= d) s += t;
    }
    __shared__ int warp_sums[32];
    if (lane == 31) warp_sums[wid] = s;
    __syncthreads();
    if (wid == 0) {
        int w = warp_sums[lane];
#pragma unroll
        for (int d = 1; d < 32; d <<= 1) {
            int t = __shfl_up_sync(0xffffffffu, w, d);
            if (lane >= d) w += t;
        }
        warp_sums[lane] = w;
    }
    __syncthreads();
    int run = s - tsum + (wid > 0 ? warp_sums[wid - 1] : 0);   // exclusive prefix

    // pass 2: emit
#pragma unroll 7
    for (int j = 0; j < C; j++) {
        int i = start + j;
        if (i < N) {
            int v = cnt[i];
            off[i] = run;
            cnt[i] = run;       // cursor for fill
            run += v;
        }
    }
    if (tid == 1023) off[N] = run;
}

__global__ void fill_kernel(const int* __restrict__ idx, int E, int view) {
    int* ecur = g_ecnt[view];
    int* ncur = g_ncnt[view];
    int stride = gridDim.x * blockDim.x;
    for (int i = blockIdx.x * blockDim.x + threadIdx.x; i < E; i += stride) {
        int n = idx[i], e = idx[E + i];
        g_eadj[atomicAdd(&ecur[e], 1)] = (unsigned short)n;
        g_nadj[atomicAdd(&ncur[n], 1)] = (unsigned short)e;
    }
}

// ---------------- pass 1: nodes -> hyperedges (fp16 rows, fp32 accum) ----------
__global__ void __launch_bounds__(256) n2e_kernel(int view) {
    const int e = (blockIdx.x * blockDim.x + threadIdx.x) >> 5;
    if (e >= N_EDGES) return;
    const int lane = threadIdx.x & 31;
    const int base = g_eoff[view][e], end = g_eoff[view][e + 1];

    float4 acc = make_float4(0.f, 0.f, 0.f, 0.f);
    for (int j0 = base; j0 < end; j0 += 32) {
        const int cnt = min(32, end - j0);
        const int myid = (lane < cnt) ? (int)g_eadj[j0 + lane] : 0;
        for (int t = 0; t < cnt; t++) {
            const int nid = __shfl_sync(0xffffffffu, myid, t);
            uint2 raw = *reinterpret_cast<const uint2*>(&g_x[(size_t)nid * COUT + lane * 4]);
            float2 f0 = __half22float2(*reinterpret_cast<__half2*>(&raw.x));
            float2 f1 = __half22float2(*reinterpret_cast<__half2*>(&raw.y));
            acc.x += f0.x; acc.y += f0.y; acc.z += f1.x; acc.w += f1.y;
        }
    }
    const float s = (end > base) ? __fdividef(1.f, (float)(end - base)) : 0.f;
    __half2 h0 = __floats2half2_rn(acc.x * s, acc.y * s);
    __half2 h1 = __floats2half2_rn(acc.z * s, acc.w * s);
    uint2 o;
    o.x = *reinterpret_cast<unsigned int*>(&h0);
    o.y = *reinterpret_cast<unsigned int*>(&h1);
    *reinterpret_cast<uint2*>(&g_edge[(size_t)e * COUT + lane * 4]) = o;
}

// ---------------- pass 2: hyperedges -> nodes (fp16 rows, fp32 accum/out) ------
// first=1: out = bias + 0.5*sum ; first=0: out += 0.5*sum (warp owns row)
__global__ void __launch_bounds__(256) e2n_kernel(const float* __restrict__ bias,
                                                  float* __restrict__ out,
                                                  int view, int first) {
    const int n = (blockIdx.x * blockDim.x + threadIdx.x) >> 5;
    if (n >= N_NODES) return;
    const int lane = threadIdx.x & 31;
    const int base = g_noff[view][n], end = g_noff[view][n + 1];

    float4 acc = make_float4(0.f, 0.f, 0.f, 0.f);
    for (int j0 = base; j0 < end; j0 += 32) {
        const int cnt = min(32, end - j0);
        const int myid = (lane < cnt) ? (int)g_nadj[j0 + lane] : 0;
        for (int t = 0; t < cnt; t++) {
            const int eid = __shfl_sync(0xffffffffu, myid, t);
            uint2 raw = *reinterpret_cast<const uint2*>(&g_edge[(size_t)eid * COUT + lane * 4]);
            float2 f0 = __half22float2(*reinterpret_cast<__half2*>(&raw.x));
            float2 f1 = __half22float2(*reinterpret_cast<__half2*>(&raw.y));
            acc.x += f0.x; acc.y += f0.y; acc.z += f1.x; acc.w += f1.y;
        }
    }
    const float c = (end > base) ? __fdividef(0.5f, (float)(end - base)) : 0.f;
    float4 r;
    if (first) r = *reinterpret_cast<const float4*>(&bias[lane * 4]);
    else       r = *reinterpret_cast<const float4*>(&out[(size_t)n * COUT + lane * 4]);
    r.x += c * acc.x; r.y += c * acc.y; r.z += c * acc.z; r.w += c * acc.w;
    *reinterpret_cast<float4*>(&out[(size_t)n * COUT + lane * 4]) = r;
}

// ---------------- launcher ----------------
extern "C" void kernel_launch(void* const* d_in, const int* in_sizes, int n_in,
                              void* d_out, int out_size) {
    const float* product  = (const float*)d_in[0];
    const float* category = (const float*)d_in[1];
    const float* av_feat  = (const float*)d_in[2];
    const int* also_view  = (const int*)d_in[3];   // int32
    const int* also_buy   = (const int*)d_in[4];
    const float* lin_w    = (const float*)d_in[5];
    const float* bias     = (const float*)d_in[6];
    float* out = (float*)d_out;

    const int E = in_sizes[3] / 2;
    const int cat_elems = in_sizes[1];
    const int av_elems = in_sizes[2];

    // GEMM x = product @ lin_w (fp16 out)
    gemm_kernel<<<(N_NODES + 127) / 128, 256>>>(product, lin_w);

    // CSR counts + offsets for BOTH views up front
    zero_cnt_kernel<<<(N_EDGES + 255) / 256, 256>>>();
    count_kernel<<<1024, 256>>>(also_view, also_buy, E);
    scan4_kernel<<<4, 1024>>>();

    const int WB = (N_EDGES * 32 + 255) / 256;
    const int NB = (N_NODES * 32 + 255) / 256;

    // ---- view 0: also_view ----
    fill_kernel<<<1024, 256>>>(also_view, E, 0);
    n2e_kernel<<<WB, 256>>>(0);
    e2n_kernel<<<NB, 256>>>(bias, out, 0, 1);

    // ---- view 1: also_buy (adjacency buffers reused) ----
    fill_kernel<<<1024, 256>>>(also_buy, E, 1);
    n2e_kernel<<<WB, 256>>>(1);
    e2n_kernel<<<NB, 256>>>(bias, out, 1, 0);

    // passthrough outputs: category, av
    cudaMemcpyAsync(out + (size_t)N_NODES * COUT, category,
                    (size_t)cat_elems * sizeof(float), cudaMemcpyDeviceToDevice, 0);
    cudaMemcpyAsync(out + (size_t)N_NODES * COUT + cat_elems, av_feat,
                    (size_t)av_elems * sizeof(float), cudaMemcpyDeviceToDevice, 0);
}

// round 8
// speedup vs baseline: 2.1788x; 1.3052x over previous
#include <cuda_runtime.h>
#include <cuda_fp16.h>

#define N_NODES 50000
#define N_EDGES 50000
#define CIN 256
#define COUT 128
#define MAXE 1600000
#define SCAN_CHUNK 2048
#define SCAN_BLOCKS 25   // ceil(50000/2048)

// ---------------- scratch (static device globals; ~50 MB total) ----------------
__device__ __align__(16) __half g_x[(size_t)N_NODES * COUT];        // 12.8 MB
__device__ __align__(16) __half g_edge[2][(size_t)N_EDGES * COUT];  // 25.6 MB
__device__ int g_ecnt[2][N_EDGES];                                  // count -> fill cursor
__device__ int g_ncnt[2][N_NODES];
__device__ int g_eoff[2][N_EDGES + 1];
__device__ int g_noff[2][N_NODES + 1];
__device__ unsigned short g_eadj[MAXE];                             // shared across views
__device__ unsigned short g_nadj[2][MAXE];                          // per view (e2n fused)
__device__ int g_part[4][SCAN_BLOCKS];

// array selector for scan kernels
__device__ __forceinline__ void sel_arr(int a, int*& cnt, int*& off) {
    if (a == 0)      { cnt = g_ecnt[0]; off = g_eoff[0]; }
    else if (a == 1) { cnt = g_ecnt[1]; off = g_eoff[1]; }
    else if (a == 2) { cnt = g_ncnt[0]; off = g_noff[0]; }
    else             { cnt = g_ncnt[1]; off = g_noff[1]; }
}

// ---------------- tf32 tensor-core GEMM: g_x = A[50000,256] @ W[256,128] ----------
__device__ __forceinline__ unsigned int f2tf32(float f) {
    unsigned int r;
    asm("cvt.rna.tf32.f32 %0, %1;" : "=r"(r) : "f"(f));
    return r;
}

__global__ void __launch_bounds__(256) gemm_tf32_kernel(const float* __restrict__ A,
                                                        const float* __restrict__ W) {
    __shared__ __align__(16) float As[128][20];    // 128 x 16, pad->20
    __shared__ __align__(16) float Bs[16][136];    // 16 x 128, pad->136

    const int tid = threadIdx.x;
    const int lane = tid & 31;
    const int warp = tid >> 5;
    const int m0 = blockIdx.x * 128;
    const int wm = (warp >> 1) * 32;   // 0,32,64,96
    const int wn = (warp & 1) * 64;    // 0,64
    const int r4 = lane >> 2;          // 0..7
    const int q4 = lane & 3;           // 0..3

    float c[2][8][4];
#pragma unroll
    for (int ma = 0; ma < 2; ma++)
#pragma unroll
        for (int na = 0; na < 8; na++)
#pragma unroll
            for (int i = 0; i < 4; i++) c[ma][na][i] = 0.0f;

    for (int k0 = 0; k0 < CIN; k0 += 16) {
#pragma unroll
        for (int l = 0; l < 2; l++) {
            int f = tid * 2 + l;                   // 0..511
            int arow = f >> 2, aq = f & 3;         // A tile 128x16
            float4 av = make_float4(0.f, 0.f, 0.f, 0.f);
            if (m0 + arow < N_NODES)
                av = *reinterpret_cast<const float4*>(&A[(size_t)(m0 + arow) * CIN + k0 + aq * 4]);
            *reinterpret_cast<float4*>(&As[arow][aq * 4]) = av;
            int brow = f >> 5, bc = f & 31;        // B tile 16x128
            *reinterpret_cast<float4*>(&Bs[brow][bc * 4]) =
                *reinterpret_cast<const float4*>(&W[(size_t)(k0 + brow) * COUT + bc * 4]);
        }
        __syncthreads();

#pragma unroll
        for (int ka = 0; ka < 2; ka++) {
            const int kb = ka * 8;
            unsigned int a[2][4], b[8][2];
#pragma unroll
            for (int ma = 0; ma < 2; ma++) {
                const int mrow = wm + ma * 16 + r4;
                a[ma][0] = f2tf32(As[mrow][kb + q4]);
                a[ma][1] = f2tf32(As[mrow + 8][kb + q4]);
                a[ma][2] = f2tf32(As[mrow][kb + q4 + 4]);
                a[ma][3] = f2tf32(As[mrow + 8][kb + q4 + 4]);
            }
#pragma unroll
            for (int na = 0; na < 8; na++) {
                const int ncol = wn + na * 8 + r4;
                b[na][0] = f2tf32(Bs[kb + q4][ncol]);
                b[na][1] = f2tf32(Bs[kb + q4 + 4][ncol]);
            }
#pragma unroll
            for (int ma = 0; ma < 2; ma++)
#pragma unroll
                for (int na = 0; na < 8; na++) {
                    asm volatile(
                        "mma.sync.aligned.m16n8k8.row.col.f32.tf32.tf32.f32 "
                        "{%0,%1,%2,%3}, {%4,%5,%6,%7}, {%8,%9}, {%0,%1,%2,%3};"
                        : "+f"(c[ma][na][0]), "+f"(c[ma][na][1]),
                          "+f"(c[ma][na][2]), "+f"(c[ma][na][3])
                        : "r"(a[ma][0]), "r"(a[ma][1]), "r"(a[ma][2]), "r"(a[ma][3]),
                          "r"(b[na][0]), "r"(b[na][1]));
                }
        }
        __syncthreads();
    }

    // store fp16
#pragma unroll
    for (int ma = 0; ma < 2; ma++) {
        const int row0 = m0 + wm + ma * 16 + r4;
        const int row1 = row0 + 8;
#pragma unroll
        for (int na = 0; na < 8; na++) {
            const int col = wn + na * 8 + q4 * 2;
            if (row0 < N_NODES) {
                __half2 h = __floats2half2_rn(c[ma][na][0], c[ma][na][1]);
                *reinterpret_cast<__half2*>(&g_x[(size_t)row0 * COUT + col]) = h;
            }
            if (row1 < N_NODES) {
                __half2 h = __floats2half2_rn(c[ma][na][2], c[ma][na][3]);
                *reinterpret_cast<__half2*>(&g_x[(size_t)row1 * COUT + col]) = h;
            }
        }
    }
}

// ---------------- CSR construction (both views) ----------------
__global__ void zero_cnt_kernel() {
    int i = blockIdx.x * blockDim.x + threadIdx.x;
    if (i < N_EDGES) { g_ecnt[0][i] = 0; g_ecnt[1][i] = 0; }
    if (i < N_NODES) { g_ncnt[0][i] = 0; g_ncnt[1][i] = 0; }
}

__global__ void count_kernel(const int* __restrict__ av, const int* __restrict__ ab, int E) {
    int stride = gridDim.x * blockDim.x;
    for (int i = blockIdx.x * blockDim.x + threadIdx.x; i < E; i += stride) {
        atomicAdd(&g_ncnt[0][av[i]], 1);
        atomicAdd(&g_ecnt[0][av[E + i]], 1);
        atomicAdd(&g_ncnt[1][ab[i]], 1);
        atomicAdd(&g_ecnt[1][ab[E + i]], 1);
    }
}

// phase 1: per-chunk partial sums. grid (SCAN_BLOCKS, 4), 256 threads.
__global__ void __launch_bounds__(256) scan_part_kernel() {
    int* cnt; int* off;
    sel_arr(blockIdx.y, cnt, off);
    const int base = blockIdx.x * SCAN_CHUNK;
    const int tid = threadIdx.x;
    int sum = 0;
#pragma unroll
    for (int j = 0; j < 8; j++) {
        int i = base + j * 256 + tid;
        if (i < 50000) sum += cnt[i];
    }
#pragma unroll
    for (int d = 16; d > 0; d >>= 1) sum += __shfl_down_sync(0xffffffffu, sum, d);
    __shared__ int ws[8];
    if ((tid & 31) == 0) ws[tid >> 5] = sum;
    __syncthreads();
    if (tid == 0) {
        int t = 0;
#pragma unroll
        for (int w = 0; w < 8; w++) t += ws[w];
        g_part[blockIdx.y][blockIdx.x] = t;
    }
}

// phase 2: scan the 25 partials per array. 1 block, 4 warps.
__global__ void __launch_bounds__(128) scan_part2_kernel() {
    const int w = threadIdx.x >> 5, lane = threadIdx.x & 31;
    int v = (lane < SCAN_BLOCKS) ? g_part[w][lane] : 0;
    int s = v;
#pragma unroll
    for (int d = 1; d < 32; d <<= 1) {
        int t = __shfl_up_sync(0xffffffffu, s, d);
        if (lane >= d) s += t;
    }
    if (lane < SCAN_BLOCKS) g_part[w][lane] = s - v;   // exclusive
    if (lane == SCAN_BLOCKS - 1) {
        int* cnt; int* off;
        sel_arr(w, cnt, off);
        off[50000] = s;                                 // total
    }
}

// phase 3: emit off[] and cursor. grid (SCAN_BLOCKS, 4), 256 threads.
__global__ void __launch_bounds__(256) scan_emit_kernel() {
    __shared__ int sh[SCAN_CHUNK];
    __shared__ int ws[8];
    int* cnt; int* off;
    sel_arr(blockIdx.y, cnt, off);
    const int base = blockIdx.x * SCAN_CHUNK;
    const int tid = threadIdx.x;
    const int lane = tid & 31, wid = tid >> 5;

#pragma unroll
    for (int j = 0; j < 8; j++) {
        int i = base + j * 256 + tid;
        sh[j * 256 + tid] = (i < 50000) ? cnt[i] : 0;
    }
    __syncthreads();

    // thread-serial scan of 8 contiguous elems
    int loc[8];
    int tsum = 0;
    const int t0 = tid * 8;
#pragma unroll
    for (int j = 0; j < 8; j++) { loc[j] = tsum; tsum += sh[t0 + j]; }

    // block exclusive scan of tsum
    int s = tsum;
#pragma unroll
    for (int d = 1; d < 32; d <<= 1) {
        int t = __shfl_up_sync(0xffffffffu, s, d);
        if (lane >= d) s += t;
    }
    if (lane == 31) ws[wid] = s;
    __syncthreads();
    int wpre = 0;
    if (wid > 0) {
#pragma unroll
        for (int w = 0; w < 7; w++) if (w < wid) wpre += ws[w];
    }
    const int tpre = s - tsum + wpre + g_part[blockIdx.y][blockIdx.x];
    __syncthreads();

#pragma unroll
    for (int j = 0; j < 8; j++) sh[t0 + j] = tpre + loc[j];
    __syncthreads();

#pragma unroll
    for (int j = 0; j < 8; j++) {
        int i = base + j * 256 + tid;
        if (i < 50000) { int v = sh[j * 256 + tid]; off[i] = v; cnt[i] = v; }
    }
}

__global__ void fill_kernel(const int* __restrict__ idx, int E, int view) {
    int* ecur = g_ecnt[view];
    int* ncur = g_ncnt[view];
    unsigned short* nadj = g_nadj[view];
    int stride = gridDim.x * blockDim.x;
    for (int i = blockIdx.x * blockDim.x + threadIdx.x; i < E; i += stride) {
        int n = idx[i], e = idx[E + i];
        g_eadj[atomicAdd(&ecur[e], 1)] = (unsigned short)n;
        nadj[atomicAdd(&ncur[n], 1)] = (unsigned short)e;
    }
}

// ---------------- pass 1: nodes -> hyperedges (fp16 rows, fp32 accum) ----------
__global__ void __launch_bounds__(256) n2e_kernel(int view) {
    const int e = (blockIdx.x * blockDim.x + threadIdx.x) >> 5;
    if (e >= N_EDGES) return;
    const int lane = threadIdx.x & 31;
    const int base = g_eoff[view][e], end = g_eoff[view][e + 1];

    float4 acc = make_float4(0.f, 0.f, 0.f, 0.f);
    for (int j0 = base; j0 < end; j0 += 32) {
        const int cnt = min(32, end - j0);
        const int myid = (lane < cnt) ? (int)g_eadj[j0 + lane] : 0;
        for (int t = 0; t < cnt; t++) {
            const int nid = __shfl_sync(0xffffffffu, myid, t);
            uint2 raw = *reinterpret_cast<const uint2*>(&g_x[(size_t)nid * COUT + lane * 4]);
            float2 f0 = __half22float2(*reinterpret_cast<__half2*>(&raw.x));
            float2 f1 = __half22float2(*reinterpret_cast<__half2*>(&raw.y));
            acc.x += f0.x; acc.y += f0.y; acc.z += f1.x; acc.w += f1.y;
        }
    }
    const float s = (end > base) ? __fdividef(1.f, (float)(end - base)) : 0.f;
    __half2 h0 = __floats2half2_rn(acc.x * s, acc.y * s);
    __half2 h1 = __floats2half2_rn(acc.z * s, acc.w * s);
    uint2 o;
    o.x = *reinterpret_cast<unsigned int*>(&h0);
    o.y = *reinterpret_cast<unsigned int*>(&h1);
    *reinterpret_cast<uint2*>(&g_edge[view][(size_t)e * COUT + lane * 4]) = o;
}

// ---------------- pass 2 fused: hyperedges -> nodes, both views + bias ----------
__global__ void __launch_bounds__(256) e2n_kernel(const float* __restrict__ bias,
                                                  float* __restrict__ out) {
    const int n = (blockIdx.x * blockDim.x + threadIdx.x) >> 5;
    if (n >= N_NODES) return;
    const int lane = threadIdx.x & 31;

    float4 r = *reinterpret_cast<const float4*>(&bias[lane * 4]);
#pragma unroll
    for (int v = 0; v < 2; v++) {
        const int base = g_noff[v][n], end = g_noff[v][n + 1];
        const __half* __restrict__ esrc = g_edge[v];
        const unsigned short* __restrict__ nadj = g_nadj[v];
        float4 acc = make_float4(0.f, 0.f, 0.f, 0.f);
        for (int j0 = base; j0 < end; j0 += 32) {
            const int cnt = min(32, end - j0);
            const int myid = (lane < cnt) ? (int)nadj[j0 + lane] : 0;
            for (int t = 0; t < cnt; t++) {
                const int eid = __shfl_sync(0xffffffffu, myid, t);
                uint2 raw = *reinterpret_cast<const uint2*>(&esrc[(size_t)eid * COUT + lane * 4]);
                float2 f0 = __half22float2(*reinterpret_cast<__half2*>(&raw.x));
                float2 f1 = __half22float2(*reinterpret_cast<__half2*>(&raw.y));
                acc.x += f0.x; acc.y += f0.y; acc.z += f1.x; acc.w += f1.y;
            }
        }
        const float c = (end > base) ? __fdividef(0.5f, (float)(end - base)) : 0.f;
        r.x += c * acc.x; r.y += c * acc.y; r.z += c * acc.z; r.w += c * acc.w;
    }
    *reinterpret_cast<float4*>(&out[(size_t)n * COUT + lane * 4]) = r;
}

// ---------------- launcher ----------------
extern "C" void kernel_launch(void* const* d_in, const int* in_sizes, int n_in,
                              void* d_out, int out_size) {
    const float* product  = (const float*)d_in[0];
    const float* category = (const float*)d_in[1];
    const float* av_feat  = (const float*)d_in[2];
    const int* also_view  = (const int*)d_in[3];   // int32
    const int* also_buy   = (const int*)d_in[4];
    const float* lin_w    = (const float*)d_in[5];
    const float* bias     = (const float*)d_in[6];
    float* out = (float*)d_out;

    const int E = in_sizes[3] / 2;
    const int cat_elems = in_sizes[1];
    const int av_elems = in_sizes[2];

    // GEMM x = product @ lin_w (tf32 tensor cores, fp16 out)
    gemm_tf32_kernel<<<(N_NODES + 127) / 128, 256>>>(product, lin_w);

    // CSR counts + offsets for BOTH views
    zero_cnt_kernel<<<(N_EDGES + 255) / 256, 256>>>();
    count_kernel<<<1024, 256>>>(also_view, also_buy, E);
    scan_part_kernel<<<dim3(SCAN_BLOCKS, 4), 256>>>();
    scan_part2_kernel<<<1, 128>>>();
    scan_emit_kernel<<<dim3(SCAN_BLOCKS, 4), 256>>>();

    const int WB = (N_EDGES * 32 + 255) / 256;
    const int NB = (N_NODES * 32 + 255) / 256;

    // view 0 then view 1 (g_eadj reused; n2e(v) before fill(v+1))
    fill_kernel<<<1024, 256>>>(also_view, E, 0);
    n2e_kernel<<<WB, 256>>>(0);
    fill_kernel<<<1024, 256>>>(also_buy, E, 1);
    n2e_kernel<<<WB, 256>>>(1);

    // fused edges->nodes (both views + bias, single store)
    e2n_kernel<<<NB, 256>>>(bias, out);

    // passthrough outputs: category, av
    cudaMemcpyAsync(out + (size_t)N_NODES * COUT, category,
                    (size_t)cat_elems * sizeof(float), cudaMemcpyDeviceToDevice, 0);
    cudaMemcpyAsync(out + (size_t)N_NODES * COUT + cat_elems, av_feat,
                    (size_t)av_elems * sizeof(float), cudaMemcpyDeviceToDevice, 0);
}

// round 9
// speedup vs baseline: 2.2873x; 1.0498x over previous
#include <cuda_runtime.h>
#include <cuda_fp16.h>

#define N_NODES 50000
#define N_EDGES 50000
#define CIN 256
#define COUT 128
#define MAXE 1600000
#define SCAN_CHUNK 2048
#define SCAN_BLOCKS 25   // ceil(50000/2048)

#define GEMM_BLOCKS 391  // ceil(50000/128)
#define CNT_BLOCKS 512
#define FILL_BLOCKS_PER_VIEW 512

// ---------------- scratch (static device globals; ~50 MB total) ----------------
__device__ __align__(16) __half g_x[(size_t)N_NODES * COUT];        // 12.8 MB
__device__ __align__(16) __half g_edge[2][(size_t)N_EDGES * COUT];  // 25.6 MB
__device__ int g_ecnt[2][N_EDGES];                                  // count -> fill cursor
__device__ int g_ncnt[2][N_NODES];
__device__ int g_eoff[2][N_EDGES + 1];
__device__ int g_noff[2][N_NODES + 1];
__device__ unsigned short g_eadj[2][MAXE];                          // node ids by edge
__device__ unsigned short g_nadj[2][MAXE];                          // edge ids by node
__device__ int g_part[4][SCAN_BLOCKS];

__device__ __forceinline__ void sel_arr(int a, int*& cnt, int*& off) {
    if (a == 0)      { cnt = g_ecnt[0]; off = g_eoff[0]; }
    else if (a == 1) { cnt = g_ecnt[1]; off = g_eoff[1]; }
    else if (a == 2) { cnt = g_ncnt[0]; off = g_noff[0]; }
    else             { cnt = g_ncnt[1]; off = g_noff[1]; }
}

__device__ __forceinline__ unsigned int f2tf32(float f) {
    unsigned int r;
    asm("cvt.rna.tf32.f32 %0, %1;" : "=r"(r) : "f"(f));
    return r;
}

// ---------------- K0: zero counters + passthrough copies -------------------------
__global__ void __launch_bounds__(256) zero_copy_kernel(const float* __restrict__ category,
                                                        const float* __restrict__ av_feat,
                                                        float* __restrict__ out,
                                                        int cat_elems, int av_elems) {
    const int ZB = (N_EDGES + 255) / 256;          // 196 zero blocks
    int bid = blockIdx.x;
    if (bid < ZB) {
        int i = bid * 256 + threadIdx.x;
        if (i < N_EDGES) { g_ecnt[0][i] = 0; g_ecnt[1][i] = 0; }
        if (i < N_NODES) { g_ncnt[0][i] = 0; g_ncnt[1][i] = 0; }
    } else {
        // copy region: [cat | av] as float4s
        const int tot4 = (cat_elems + av_elems) >> 2;
        int i = (bid - ZB) * 256 + threadIdx.x;
        if (i < tot4) {
            const int cat4 = cat_elems >> 2;
            float4 v;
            if (i < cat4) v = reinterpret_cast<const float4*>(category)[i];
            else          v = reinterpret_cast<const float4*>(av_feat)[i - cat4];
            reinterpret_cast<float4*>(out + (size_t)N_NODES * COUT)[i] = v;
        }
    }
}

// ---------------- K1: tf32 GEMM (blocks [0,391)) + count (blocks [391,903)) -----
__global__ void __launch_bounds__(256) gemm_count_kernel(const float* __restrict__ A,
                                                         const float* __restrict__ W,
                                                         const int* __restrict__ av,
                                                         const int* __restrict__ ab,
                                                         int E) {
    if (blockIdx.x >= GEMM_BLOCKS) {
        // ---- count path ----
        const int stride = CNT_BLOCKS * 256;
        for (int i = (blockIdx.x - GEMM_BLOCKS) * 256 + threadIdx.x; i < E; i += stride) {
            atomicAdd(&g_ncnt[0][av[i]], 1);
            atomicAdd(&g_ecnt[0][av[E + i]], 1);
            atomicAdd(&g_ncnt[1][ab[i]], 1);
            atomicAdd(&g_ecnt[1][ab[E + i]], 1);
        }
        return;
    }

    // ---- GEMM path ----
    __shared__ __align__(16) float As[128][20];
    __shared__ __align__(16) float Bs[16][136];

    const int tid = threadIdx.x;
    const int lane = tid & 31;
    const int warp = tid >> 5;
    const int m0 = blockIdx.x * 128;
    const int wm = (warp >> 1) * 32;
    const int wn = (warp & 1) * 64;
    const int r4 = lane >> 2;
    const int q4 = lane & 3;

    float c[2][8][4];
#pragma unroll
    for (int ma = 0; ma < 2; ma++)
#pragma unroll
        for (int na = 0; na < 8; na++)
#pragma unroll
            for (int i = 0; i < 4; i++) c[ma][na][i] = 0.0f;

    for (int k0 = 0; k0 < CIN; k0 += 16) {
#pragma unroll
        for (int l = 0; l < 2; l++) {
            int f = tid * 2 + l;
            int arow = f >> 2, aq = f & 3;
            float4 avv = make_float4(0.f, 0.f, 0.f, 0.f);
            if (m0 + arow < N_NODES)
                avv = *reinterpret_cast<const float4*>(&A[(size_t)(m0 + arow) * CIN + k0 + aq * 4]);
            *reinterpret_cast<float4*>(&As[arow][aq * 4]) = avv;
            int brow = f >> 5, bc = f & 31;
            *reinterpret_cast<float4*>(&Bs[brow][bc * 4]) =
                *reinterpret_cast<const float4*>(&W[(size_t)(k0 + brow) * COUT + bc * 4]);
        }
        __syncthreads();

#pragma unroll
        for (int ka = 0; ka < 2; ka++) {
            const int kb = ka * 8;
            unsigned int a[2][4], b[8][2];
#pragma unroll
            for (int ma = 0; ma < 2; ma++) {
                const int mrow = wm + ma * 16 + r4;
                a[ma][0] = f2tf32(As[mrow][kb + q4]);
                a[ma][1] = f2tf32(As[mrow + 8][kb + q4]);
                a[ma][2] = f2tf32(As[mrow][kb + q4 + 4]);
                a[ma][3] = f2tf32(As[mrow + 8][kb + q4 + 4]);
            }
#pragma unroll
            for (int na = 0; na < 8; na++) {
                const int ncol = wn + na * 8 + r4;
                b[na][0] = f2tf32(Bs[kb + q4][ncol]);
                b[na][1] = f2tf32(Bs[kb + q4 + 4][ncol]);
            }
#pragma unroll
            for (int ma = 0; ma < 2; ma++)
#pragma unroll
                for (int na = 0; na < 8; na++) {
                    asm volatile(
                        "mma.sync.aligned.m16n8k8.row.col.f32.tf32.tf32.f32 "
                        "{%0,%1,%2,%3}, {%4,%5,%6,%7}, {%8,%9}, {%0,%1,%2,%3};"
                        : "+f"(c[ma][na][0]), "+f"(c[ma][na][1]),
                          "+f"(c[ma][na][2]), "+f"(c[ma][na][3])
                        : "r"(a[ma][0]), "r"(a[ma][1]), "r"(a[ma][2]), "r"(a[ma][3]),
                          "r"(b[na][0]), "r"(b[na][1]));
                }
        }
        __syncthreads();
    }

#pragma unroll
    for (int ma = 0; ma < 2; ma++) {
        const int row0 = m0 + wm + ma * 16 + r4;
        const int row1 = row0 + 8;
#pragma unroll
        for (int na = 0; na < 8; na++) {
            const int col = wn + na * 8 + q4 * 2;
            if (row0 < N_NODES) {
                __half2 h = __floats2half2_rn(c[ma][na][0], c[ma][na][1]);
                *reinterpret_cast<__half2*>(&g_x[(size_t)row0 * COUT + col]) = h;
            }
            if (row1 < N_NODES) {
                __half2 h = __floats2half2_rn(c[ma][na][2], c[ma][na][3]);
                *reinterpret_cast<__half2*>(&g_x[(size_t)row1 * COUT + col]) = h;
            }
        }
    }
}

// ---------------- scan: 3 phases ----------------
__global__ void __launch_bounds__(256) scan_part_kernel() {
    int* cnt; int* off;
    sel_arr(blockIdx.y, cnt, off);
    const int base = blockIdx.x * SCAN_CHUNK;
    const int tid = threadIdx.x;
    int sum = 0;
#pragma unroll
    for (int j = 0; j < 8; j++) {
        int i = base + j * 256 + tid;
        if (i < 50000) sum += cnt[i];
    }
#pragma unroll
    for (int d = 16; d > 0; d >>= 1) sum += __shfl_down_sync(0xffffffffu, sum, d);
    __shared__ int ws[8];
    if ((tid & 31) == 0) ws[tid >> 5] = sum;
    __syncthreads();
    if (tid == 0) {
        int t = 0;
#pragma unroll
        for (int w = 0; w < 8; w++) t += ws[w];
        g_part[blockIdx.y][blockIdx.x] = t;
    }
}

__global__ void __launch_bounds__(128) scan_part2_kernel() {
    const int w = threadIdx.x >> 5, lane = threadIdx.x & 31;
    int v = (lane < SCAN_BLOCKS) ? g_part[w][lane] : 0;
    int s = v;
#pragma unroll
    for (int d = 1; d < 32; d <<= 1) {
        int t = __shfl_up_sync(0xffffffffu, s, d);
        if (lane >= d) s += t;
    }
    if (lane < SCAN_BLOCKS) g_part[w][lane] = s - v;
    if (lane == SCAN_BLOCKS - 1) {
        int* cnt; int* off;
        sel_arr(w, cnt, off);
        off[50000] = s;
    }
}

__global__ void __launch_bounds__(256) scan_emit_kernel() {
    __shared__ int sh[SCAN_CHUNK];
    __shared__ int ws[8];
    int* cnt; int* off;
    sel_arr(blockIdx.y, cnt, off);
    const int base = blockIdx.x * SCAN_CHUNK;
    const int tid = threadIdx.x;
    const int lane = tid & 31, wid = tid >> 5;

#pragma unroll
    for (int j = 0; j < 8; j++) {
        int i = base + j * 256 + tid;
        sh[j * 256 + tid] = (i < 50000) ? cnt[i] : 0;
    }
    __syncthreads();

    int loc[8];
    int tsum = 0;
    const int t0 = tid * 8;
#pragma unroll
    for (int j = 0; j < 8; j++) { loc[j] = tsum; tsum += sh[t0 + j]; }

    int s = tsum;
#pragma unroll
    for (int d = 1; d < 32; d <<= 1) {
        int t = __shfl_up_sync(0xffffffffu, s, d);
        if (lane >= d) s += t;
    }
    if (lane == 31) ws[wid] = s;
    __syncthreads();
    int wpre = 0;
#pragma unroll
    for (int w = 0; w < 7; w++) if (w < wid) wpre += ws[w];
    const int tpre = s - tsum + wpre + g_part[blockIdx.y][blockIdx.x];
    __syncthreads();

#pragma unroll
    for (int j = 0; j < 8; j++) sh[t0 + j] = tpre + loc[j];
    __syncthreads();

#pragma unroll
    for (int j = 0; j < 8; j++) {
        int i = base + j * 256 + tid;
        if (i < 50000) { int v = sh[j * 256 + tid]; off[i] = v; cnt[i] = v; }
    }
}

// ---------------- K5: fill both views (block-partitioned) -----------------------
__global__ void __launch_bounds__(256) fill2_kernel(const int* __restrict__ av,
                                                    const int* __restrict__ ab, int E) {
    const int view = (blockIdx.x >= FILL_BLOCKS_PER_VIEW) ? 1 : 0;
    const int* idx = view ? ab : av;
    int* ecur = g_ecnt[view];
    int* ncur = g_ncnt[view];
    unsigned short* eadj = g_eadj[view];
    unsigned short* nadj = g_nadj[view];
    const int b0 = blockIdx.x - view * FILL_BLOCKS_PER_VIEW;
    const int stride = FILL_BLOCKS_PER_VIEW * 256;
    for (int i = b0 * 256 + threadIdx.x; i < E; i += stride) {
        int n = idx[i], e = idx[E + i];
        eadj[atomicAdd(&ecur[e], 1)] = (unsigned short)n;
        nadj[atomicAdd(&ncur[n], 1)] = (unsigned short)e;
    }
}

// ---------------- K6: n2e both views (warp per (view,edge)) ---------------------
__global__ void __launch_bounds__(256) n2e2_kernel() {
    const int gw = (blockIdx.x * blockDim.x + threadIdx.x) >> 5;
    if (gw >= 2 * N_EDGES) return;
    const int view = (gw >= N_EDGES) ? 1 : 0;
    const int e = gw - view * N_EDGES;
    const int lane = threadIdx.x & 31;
    const int base = g_eoff[view][e], end = g_eoff[view][e + 1];
    const unsigned short* __restrict__ eadj = g_eadj[view];

    float4 acc = make_float4(0.f, 0.f, 0.f, 0.f);
    for (int j0 = base; j0 < end; j0 += 32) {
        const int cnt = min(32, end - j0);
        const int myid = (lane < cnt) ? (int)eadj[j0 + lane] : 0;
        for (int t = 0; t < cnt; t++) {
            const int nid = __shfl_sync(0xffffffffu, myid, t);
            uint2 raw = *reinterpret_cast<const uint2*>(&g_x[(size_t)nid * COUT + lane * 4]);
            float2 f0 = __half22float2(*reinterpret_cast<__half2*>(&raw.x));
            float2 f1 = __half22float2(*reinterpret_cast<__half2*>(&raw.y));
            acc.x += f0.x; acc.y += f0.y; acc.z += f1.x; acc.w += f1.y;
        }
    }
    const float s = (end > base) ? __fdividef(1.f, (float)(end - base)) : 0.f;
    __half2 h0 = __floats2half2_rn(acc.x * s, acc.y * s);
    __half2 h1 = __floats2half2_rn(acc.z * s, acc.w * s);
    uint2 o;
    o.x = *reinterpret_cast<unsigned int*>(&h0);
    o.y = *reinterpret_cast<unsigned int*>(&h1);
    *reinterpret_cast<uint2*>(&g_edge[view][(size_t)e * COUT + lane * 4]) = o;
}

// ---------------- K7: e2n fused (both views + bias, single store) ---------------
__global__ void __launch_bounds__(256) e2n_kernel(const float* __restrict__ bias,
                                                  float* __restrict__ out) {
    const int n = (blockIdx.x * blockDim.x + threadIdx.x) >> 5;
    if (n >= N_NODES) return;
    const int lane = threadIdx.x & 31;

    float4 r = *reinterpret_cast<const float4*>(&bias[lane * 4]);
#pragma unroll
    for (int v = 0; v < 2; v++) {
        const int base = g_noff[v][n], end = g_noff[v][n + 1];
        const __half* __restrict__ esrc = g_edge[v];
        const unsigned short* __restrict__ nadj = g_nadj[v];
        float4 acc = make_float4(0.f, 0.f, 0.f, 0.f);
        for (int j0 = base; j0 < end; j0 += 32) {
            const int cnt = min(32, end - j0);
            const int myid = (lane < cnt) ? (int)nadj[j0 + lane] : 0;
            for (int t = 0; t < cnt; t++) {
                const int eid = __shfl_sync(0xffffffffu, myid, t);
                uint2 raw = *reinterpret_cast<const uint2*>(&esrc[(size_t)eid * COUT + lane * 4]);
                float2 f0 = __half22float2(*reinterpret_cast<__half2*>(&raw.x));
                float2 f1 = __half22float2(*reinterpret_cast<__half2*>(&raw.y));
                acc.x += f0.x; acc.y += f0.y; acc.z += f1.x; acc.w += f1.y;
            }
        }
        const float c = (end > base) ? __fdividef(0.5f, (float)(end - base)) : 0.f;
        r.x += c * acc.x; r.y += c * acc.y; r.z += c * acc.z; r.w += c * acc.w;
    }
    *reinterpret_cast<float4*>(&out[(size_t)n * COUT + lane * 4]) = r;
}

// ---------------- launcher ----------------
extern "C" void kernel_launch(void* const* d_in, const int* in_sizes, int n_in,
                              void* d_out, int out_size) {
    const float* product  = (const float*)d_in[0];
    const float* category = (const float*)d_in[1];
    const float* av_feat  = (const float*)d_in[2];
    const int* also_view  = (const int*)d_in[3];   // int32
    const int* also_buy   = (const int*)d_in[4];
    const float* lin_w    = (const float*)d_in[5];
    const float* bias     = (const float*)d_in[6];
    float* out = (float*)d_out;

    const int E = in_sizes[3] / 2;
    const int cat_elems = in_sizes[1];
    const int av_elems = in_sizes[2];

    // K0: zero counters + passthrough copies
    const int ZB = (N_EDGES + 255) / 256;
    const int CPB = (((cat_elems + av_elems) >> 2) + 255) / 256;
    zero_copy_kernel<<<ZB + CPB, 256>>>(category, av_feat, out, cat_elems, av_elems);

    // K1: GEMM + count concurrently (block-partitioned)
    gemm_count_kernel<<<GEMM_BLOCKS + CNT_BLOCKS, 256>>>(product, lin_w,
                                                         also_view, also_buy, E);

    // scan (3 small kernels)
    scan_part_kernel<<<dim3(SCAN_BLOCKS, 4), 256>>>();
    scan_part2_kernel<<<1, 128>>>();
    scan_emit_kernel<<<dim3(SCAN_BLOCKS, 4), 256>>>();

    // K5: fill both views
    fill2_kernel<<<2 * FILL_BLOCKS_PER_VIEW, 256>>>(also_view, also_buy, E);

    // K6: n2e both views
    n2e2_kernel<<<(2 * N_EDGES * 32 + 255) / 256, 256>>>();

    // K7: e2n fused
    e2n_kernel<<<(N_NODES * 32 + 255) / 256, 256>>>(bias, out);
}

// round 10
// speedup vs baseline: 2.3655x; 1.0342x over previous
#include <cuda_runtime.h>
#include <cuda_fp16.h>

#define N_NODES 50000
#define N_EDGES 50000
#define CIN 256
#define COUT 128
#define MAXE 1600000
#define SCAN_CHUNK 2048
#define SCAN_BLOCKS 25   // ceil(50000/2048)

#define GEMM_BLOCKS 391  // ceil(50000/128)
#define CNT_BLOCKS 512
#define FILL_BLOCKS_PER_VIEW 512

// ---------------- scratch (static device globals; ~50 MB total) ----------------
__device__ __align__(16) __half g_x[(size_t)N_NODES * COUT];        // 12.8 MB
__device__ __align__(16) __half g_edge[2][(size_t)N_EDGES * COUT];  // 25.6 MB
__device__ int g_ecnt[2][N_EDGES];                                  // count -> fill cursor
__device__ int g_ncnt[2][N_NODES];
__device__ int g_eoff[2][N_EDGES + 1];
__device__ int g_noff[2][N_NODES + 1];
__device__ unsigned short g_eadj[2][MAXE];                          // node ids by edge
__device__ unsigned short g_nadj[2][MAXE];                          // edge ids by node
__device__ int g_part[4][SCAN_BLOCKS];

__device__ __forceinline__ void sel_arr(int a, int*& cnt, int*& off) {
    if (a == 0)      { cnt = g_ecnt[0]; off = g_eoff[0]; }
    else if (a == 1) { cnt = g_ecnt[1]; off = g_eoff[1]; }
    else if (a == 2) { cnt = g_ncnt[0]; off = g_noff[0]; }
    else             { cnt = g_ncnt[1]; off = g_noff[1]; }
}

__device__ __forceinline__ unsigned int f2tf32(float f) {
    unsigned int r;
    asm("cvt.rna.tf32.f32 %0, %1;" : "=r"(r) : "f"(f));
    return r;
}

// fp16 row accumulate helper
__device__ __forceinline__ void acc_row(const __half* __restrict__ src, size_t rowbase,
                                        int lane, float4& acc) {
    uint2 raw = *reinterpret_cast<const uint2*>(&src[rowbase + lane * 4]);
    float2 f0 = __half22float2(*reinterpret_cast<__half2*>(&raw.x));
    float2 f1 = __half22float2(*reinterpret_cast<__half2*>(&raw.y));
    acc.x += f0.x; acc.y += f0.y; acc.z += f1.x; acc.w += f1.y;
}

// ---------------- K0: zero counters only ----------------
__global__ void zero_kernel() {
    int i = blockIdx.x * blockDim.x + threadIdx.x;
    if (i < N_EDGES) { g_ecnt[0][i] = 0; g_ecnt[1][i] = 0; }
    if (i < N_NODES) { g_ncnt[0][i] = 0; g_ncnt[1][i] = 0; }
}

// ---------------- K1: GEMM [0,391) + count [391,903) + copy [903,...) ----------
__global__ void __launch_bounds__(256) gemm_count_copy_kernel(
        const float* __restrict__ A, const float* __restrict__ W,
        const int* __restrict__ av, const int* __restrict__ ab, int E,
        const float* __restrict__ category, const float* __restrict__ av_feat,
        float* __restrict__ out, int cat_elems, int av_elems) {

    if (blockIdx.x >= GEMM_BLOCKS + CNT_BLOCKS) {
        // ---- copy path: [cat | av] as float4s ----
        const int tot4 = (cat_elems + av_elems) >> 2;
        int i = (blockIdx.x - GEMM_BLOCKS - CNT_BLOCKS) * 256 + threadIdx.x;
        if (i < tot4) {
            const int cat4 = cat_elems >> 2;
            float4 v;
            if (i < cat4) v = reinterpret_cast<const float4*>(category)[i];
            else          v = reinterpret_cast<const float4*>(av_feat)[i - cat4];
            reinterpret_cast<float4*>(out + (size_t)N_NODES * COUT)[i] = v;
        }
        return;
    }
    if (blockIdx.x >= GEMM_BLOCKS) {
        // ---- count path ----
        const int stride = CNT_BLOCKS * 256;
        for (int i = (blockIdx.x - GEMM_BLOCKS) * 256 + threadIdx.x; i < E; i += stride) {
            atomicAdd(&g_ncnt[0][__ldg(&av[i])], 1);
            atomicAdd(&g_ecnt[0][__ldg(&av[E + i])], 1);
            atomicAdd(&g_ncnt[1][__ldg(&ab[i])], 1);
            atomicAdd(&g_ecnt[1][__ldg(&ab[E + i])], 1);
        }
        return;
    }

    // ---- GEMM path ----
    __shared__ __align__(16) float As[128][20];
    __shared__ __align__(16) float Bs[16][136];

    const int tid = threadIdx.x;
    const int lane = tid & 31;
    const int warp = tid >> 5;
    const int m0 = blockIdx.x * 128;
    const int wm = (warp >> 1) * 32;
    const int wn = (warp & 1) * 64;
    const int r4 = lane >> 2;
    const int q4 = lane & 3;

    float c[2][8][4];
#pragma unroll
    for (int ma = 0; ma < 2; ma++)
#pragma unroll
        for (int na = 0; na < 8; na++)
#pragma unroll
            for (int i = 0; i < 4; i++) c[ma][na][i] = 0.0f;

    for (int k0 = 0; k0 < CIN; k0 += 16) {
#pragma unroll
        for (int l = 0; l < 2; l++) {
            int f = tid * 2 + l;
            int arow = f >> 2, aq = f & 3;
            float4 avv = make_float4(0.f, 0.f, 0.f, 0.f);
            if (m0 + arow < N_NODES)
                avv = *reinterpret_cast<const float4*>(&A[(size_t)(m0 + arow) * CIN + k0 + aq * 4]);
            *reinterpret_cast<float4*>(&As[arow][aq * 4]) = avv;
            int brow = f >> 5, bc = f & 31;
            *reinterpret_cast<float4*>(&Bs[brow][bc * 4]) =
                *reinterpret_cast<const float4*>(&W[(size_t)(k0 + brow) * COUT + bc * 4]);
        }
        __syncthreads();

#pragma unroll
        for (int ka = 0; ka < 2; ka++) {
            const int kb = ka * 8;
            unsigned int a[2][4], b[8][2];
#pragma unroll
            for (int ma = 0; ma < 2; ma++) {
                const int mrow = wm + ma * 16 + r4;
                a[ma][0] = f2tf32(As[mrow][kb + q4]);
                a[ma][1] = f2tf32(As[mrow + 8][kb + q4]);
                a[ma][2] = f2tf32(As[mrow][kb + q4 + 4]);
                a[ma][3] = f2tf32(As[mrow + 8][kb + q4 + 4]);
            }
#pragma unroll
            for (int na = 0; na < 8; na++) {
                const int ncol = wn + na * 8 + r4;
                b[na][0] = f2tf32(Bs[kb + q4][ncol]);
                b[na][1] = f2tf32(Bs[kb + q4 + 4][ncol]);
            }
#pragma unroll
            for (int ma = 0; ma < 2; ma++)
#pragma unroll
                for (int na = 0; na < 8; na++) {
                    asm volatile(
                        "mma.sync.aligned.m16n8k8.row.col.f32.tf32.tf32.f32 "
                        "{%0,%1,%2,%3}, {%4,%5,%6,%7}, {%8,%9}, {%0,%1,%2,%3};"
                        : "+f"(c[ma][na][0]), "+f"(c[ma][na][1]),
                          "+f"(c[ma][na][2]), "+f"(c[ma][na][3])
                        : "r"(a[ma][0]), "r"(a[ma][1]), "r"(a[ma][2]), "r"(a[ma][3]),
                          "r"(b[na][0]), "r"(b[na][1]));
                }
        }
        __syncthreads();
    }

#pragma unroll
    for (int ma = 0; ma < 2; ma++) {
        const int row0 = m0 + wm + ma * 16 + r4;
        const int row1 = row0 + 8;
#pragma unroll
        for (int na = 0; na < 8; na++) {
            const int col = wn + na * 8 + q4 * 2;
            if (row0 < N_NODES) {
                __half2 h = __floats2half2_rn(c[ma][na][0], c[ma][na][1]);
                *reinterpret_cast<__half2*>(&g_x[(size_t)row0 * COUT + col]) = h;
            }
            if (row1 < N_NODES) {
                __half2 h = __floats2half2_rn(c[ma][na][2], c[ma][na][3]);
                *reinterpret_cast<__half2*>(&g_x[(size_t)row1 * COUT + col]) = h;
            }
        }
    }
}

// ---------------- scan: 3 phases ----------------
__global__ void __launch_bounds__(256) scan_part_kernel() {
    int* cnt; int* off;
    sel_arr(blockIdx.y, cnt, off);
    const int base = blockIdx.x * SCAN_CHUNK;
    const int tid = threadIdx.x;
    int sum = 0;
#pragma unroll
    for (int j = 0; j < 8; j++) {
        int i = base + j * 256 + tid;
        if (i < 50000) sum += cnt[i];
    }
#pragma unroll
    for (int d = 16; d > 0; d >>= 1) sum += __shfl_down_sync(0xffffffffu, sum, d);
    __shared__ int ws[8];
    if ((tid & 31) == 0) ws[tid >> 5] = sum;
    __syncthreads();
    if (tid == 0) {
        int t = 0;
#pragma unroll
        for (int w = 0; w < 8; w++) t += ws[w];
        g_part[blockIdx.y][blockIdx.x] = t;
    }
}

__global__ void __launch_bounds__(128) scan_part2_kernel() {
    const int w = threadIdx.x >> 5, lane = threadIdx.x & 31;
    int v = (lane < SCAN_BLOCKS) ? g_part[w][lane] : 0;
    int s = v;
#pragma unroll
    for (int d = 1; d < 32; d <<= 1) {
        int t = __shfl_up_sync(0xffffffffu, s, d);
        if (lane >= d) s += t;
    }
    if (lane < SCAN_BLOCKS) g_part[w][lane] = s - v;
    if (lane == SCAN_BLOCKS - 1) {
        int* cnt; int* off;
        sel_arr(w, cnt, off);
        off[50000] = s;
    }
}

__global__ void __launch_bounds__(256) scan_emit_kernel() {
    __shared__ int sh[SCAN_CHUNK];
    __shared__ int ws[8];
    int* cnt; int* off;
    sel_arr(blockIdx.y, cnt, off);
    const int base = blockIdx.x * SCAN_CHUNK;
    const int tid = threadIdx.x;
    const int lane = tid & 31, wid = tid >> 5;

#pragma unroll
    for (int j = 0; j < 8; j++) {
        int i = base + j * 256 + tid;
        sh[j * 256 + tid] = (i < 50000) ? cnt[i] : 0;
    }
    __syncthreads();

    int loc[8];
    int tsum = 0;
    const int t0 = tid * 8;
#pragma unroll
    for (int j = 0; j < 8; j++) { loc[j] = tsum; tsum += sh[t0 + j]; }

    int s = tsum;
#pragma unroll
    for (int d = 1; d < 32; d <<= 1) {
        int t = __shfl_up_sync(0xffffffffu, s, d);
        if (lane >= d) s += t;
    }
    if (lane == 31) ws[wid] = s;
    __syncthreads();
    int wpre = 0;
#pragma unroll
    for (int w = 0; w < 7; w++) if (w < wid) wpre += ws[w];
    const int tpre = s - tsum + wpre + g_part[blockIdx.y][blockIdx.x];
    __syncthreads();

#pragma unroll
    for (int j = 0; j < 8; j++) sh[t0 + j] = tpre + loc[j];
    __syncthreads();

#pragma unroll
    for (int j = 0; j < 8; j++) {
        int i = base + j * 256 + tid;
        if (i < 50000) { int v = sh[j * 256 + tid]; off[i] = v; cnt[i] = v; }
    }
}

// ---------------- K5: fill both views (block-partitioned) -----------------------
__global__ void __launch_bounds__(256) fill2_kernel(const int* __restrict__ av,
                                                    const int* __restrict__ ab, int E) {
    const int view = (blockIdx.x >= FILL_BLOCKS_PER_VIEW) ? 1 : 0;
    const int* idx = view ? ab : av;
    int* ecur = g_ecnt[view];
    int* ncur = g_ncnt[view];
    unsigned short* eadj = g_eadj[view];
    unsigned short* nadj = g_nadj[view];
    const int b0 = blockIdx.x - view * FILL_BLOCKS_PER_VIEW;
    const int stride = FILL_BLOCKS_PER_VIEW * 256;
    for (int i = b0 * 256 + threadIdx.x; i < E; i += stride) {
        int n = __ldg(&idx[i]), e = __ldg(&idx[E + i]);
        eadj[atomicAdd(&ecur[e], 1)] = (unsigned short)n;
        nadj[atomicAdd(&ncur[n], 1)] = (unsigned short)e;
    }
}

// ---------------- K6: n2e both views (warp per (view,edge), 2-way ILP) ----------
__global__ void __launch_bounds__(256) n2e2_kernel() {
    const int gw = (blockIdx.x * blockDim.x + threadIdx.x) >> 5;
    if (gw >= 2 * N_EDGES) return;
    const int view = (gw >= N_EDGES) ? 1 : 0;
    const int e = gw - view * N_EDGES;
    const int lane = threadIdx.x & 31;
    const int base = g_eoff[view][e], end = g_eoff[view][e + 1];
    const unsigned short* __restrict__ eadj = g_eadj[view];

    float4 acc0 = make_float4(0.f, 0.f, 0.f, 0.f);
    float4 acc1 = make_float4(0.f, 0.f, 0.f, 0.f);
    for (int j0 = base; j0 < end; j0 += 32) {
        const int cnt = min(32, end - j0);
        const int myid = (lane < cnt) ? (int)eadj[j0 + lane] : 0;
        int t = 0;
        for (; t + 2 <= cnt; t += 2) {
            const int id0 = __shfl_sync(0xffffffffu, myid, t);
            const int id1 = __shfl_sync(0xffffffffu, myid, t + 1);
            acc_row(g_x, (size_t)id0 * COUT, lane, acc0);
            acc_row(g_x, (size_t)id1 * COUT, lane, acc1);
        }
        if (t < cnt) {
            const int id0 = __shfl_sync(0xffffffffu, myid, t);
            acc_row(g_x, (size_t)id0 * COUT, lane, acc0);
        }
    }
    acc0.x += acc1.x; acc0.y += acc1.y; acc0.z += acc1.z; acc0.w += acc1.w;
    const float s = (end > base) ? __fdividef(1.f, (float)(end - base)) : 0.f;
    __half2 h0 = __floats2half2_rn(acc0.x * s, acc0.y * s);
    __half2 h1 = __floats2half2_rn(acc0.z * s, acc0.w * s);
    uint2 o;
    o.x = *reinterpret_cast<unsigned int*>(&h0);
    o.y = *reinterpret_cast<unsigned int*>(&h1);
    *reinterpret_cast<uint2*>(&g_edge[view][(size_t)e * COUT + lane * 4]) = o;
}

// ---------------- K7: e2n fused (both views + bias, 2-way ILP) ------------------
__global__ void __launch_bounds__(256) e2n_kernel(const float* __restrict__ bias,
                                                  float* __restrict__ out) {
    const int n = (blockIdx.x * blockDim.x + threadIdx.x) >> 5;
    if (n >= N_NODES) return;
    const int lane = threadIdx.x & 31;

    float4 r = *reinterpret_cast<const float4*>(&bias[lane * 4]);
#pragma unroll
    for (int v = 0; v < 2; v++) {
        const int base = g_noff[v][n], end = g_noff[v][n + 1];
        const __half* __restrict__ esrc = g_edge[v];
        const unsigned short* __restrict__ nadj = g_nadj[v];
        float4 acc0 = make_float4(0.f, 0.f, 0.f, 0.f);
        float4 acc1 = make_float4(0.f, 0.f, 0.f, 0.f);
        for (int j0 = base; j0 < end; j0 += 32) {
            const int cnt = min(32, end - j0);
            const int myid = (lane < cnt) ? (int)nadj[j0 + lane] : 0;
            int t = 0;
            for (; t + 2 <= cnt; t += 2) {
                const int id0 = __shfl_sync(0xffffffffu, myid, t);
                const int id1 = __shfl_sync(0xffffffffu, myid, t + 1);
                acc_row(esrc, (size_t)id0 * COUT, lane, acc0);
                acc_row(esrc, (size_t)id1 * COUT, lane, acc1);
            }
            if (t < cnt) {
                const int id0 = __shfl_sync(0xffffffffu, myid, t);
                acc_row(esrc, (size_t)id0 * COUT, lane, acc0);
            }
        }
        acc0.x += acc1.x; acc0.y += acc1.y; acc0.z += acc1.z; acc0.w += acc1.w;
        const float c = (end > base) ? __fdividef(0.5f, (float)(end - base)) : 0.f;
        r.x += c * acc0.x; r.y += c * acc0.y; r.z += c * acc0.z; r.w += c * acc0.w;
    }
    *reinterpret_cast<float4*>(&out[(size_t)n * COUT + lane * 4]) = r;
}

// ---------------- launcher ----------------
extern "C" void kernel_launch(void* const* d_in, const int* in_sizes, int n_in,
                              void* d_out, int out_size) {
    const float* product  = (const float*)d_in[0];
    const float* category = (const float*)d_in[1];
    const float* av_feat  = (const float*)d_in[2];
    const int* also_view  = (const int*)d_in[3];   // int32
    const int* also_buy   = (const int*)d_in[4];
    const float* lin_w    = (const float*)d_in[5];
    const float* bias     = (const float*)d_in[6];
    float* out = (float*)d_out;

    const int E = in_sizes[3] / 2;
    const int cat_elems = in_sizes[1];
    const int av_elems = in_sizes[2];

    // K0: zero counters (must precede count)
    zero_kernel<<<(N_EDGES + 255) / 256, 256>>>();

    // K1: GEMM + count + passthrough copies, one wave
    const int CPB = (((cat_elems + av_elems) >> 2) + 255) / 256;
    gemm_count_copy_kernel<<<GEMM_BLOCKS + CNT_BLOCKS + CPB, 256>>>(
        product, lin_w, also_view, also_buy, E,
        category, av_feat, out, cat_elems, av_elems);

    // scan (3 small kernels)
    scan_part_kernel<<<dim3(SCAN_BLOCKS, 4), 256>>>();
    scan_part2_kernel<<<1, 128>>>();
    scan_emit_kernel<<<dim3(SCAN_BLOCKS, 4), 256>>>();

    // K5: fill both views
    fill2_kernel<<<2 * FILL_BLOCKS_PER_VIEW, 256>>>(also_view, also_buy, E);

    // K6: n2e both views
    n2e2_kernel<<<(2 * N_EDGES * 32 + 255) / 256, 256>>>();

    // K7: e2n fused
    e2n_kernel<<<(N_NODES * 32 + 255) / 256, 256>>>(bias, out);
}